// round 17
// baseline (speedup 1.0000x reference)
#include <cuda_runtime.h>
#include <cuda_fp16.h>
#include <math.h>

// Problem constants (fixed by the dataset)
#define Bb   4
#define Ss   2048
#define Dd   512
#define Hh   8
#define DK   64
#define Rr   8
#define TR   16
#define NBH  (Bb*Hh)                // 32
#define NNODES (NBH*Ss)             // 65536
#define NEDGE  (NBH*TR*Ss)          // 1048576
#define MROWS (Bb*Ss)               // 8192

// ---------------- scratch (device globals; no allocation allowed) -------------
__device__ float g_q[NBH*Ss*DK];
__device__ float g_k[NBH*Ss*DK];
__device__ float g_v[NBH*Ss*DK];
__device__ int   g_cnt[NNODES];
__device__ int   g_off[NBH*(Ss+1)];
__device__ int   g_info[NEDGE];
__device__ __align__(16) __half g_ah[3*MROWS*Dd];   // fp16 inputs (q,k,v)
__device__ __align__(16) __half g_wh[4*Dd*Dd];      // weight hi
__device__ __align__(16) __half g_wl[4*Dd*Dd];      // weight lo
__device__ __align__(16) __half g_atth[MROWS*Dd];   // attn output fp16

// ======================= helpers =============================================
__device__ __forceinline__ unsigned su32(const void* p){
    unsigned a;
    asm("{ .reg .u64 t; cvta.to.shared.u64 t, %1; cvt.u32.u64 %0, t; }"
        : "=r"(a) : "l"(p));
    return a;
}
__device__ __forceinline__ void cpa16(unsigned dst, const void* src){
    asm volatile("cp.async.cg.shared.global [%0], [%1], 16;"
                 :: "r"(dst), "l"(src));
}
__device__ __forceinline__ void cpa_commit(){
    asm volatile("cp.async.commit_group;");
}
__device__ __forceinline__ void cpa_wait2(){
    asm volatile("cp.async.wait_group 2;");
}
__device__ __forceinline__ void ldmx4(unsigned* r, unsigned addr){
    asm volatile("ldmatrix.sync.aligned.m8n8.x4.shared.b16 {%0,%1,%2,%3}, [%4];"
                 : "=r"(r[0]), "=r"(r[1]), "=r"(r[2]), "=r"(r[3]) : "r"(addr));
}
__device__ __forceinline__ void mma_f16(float* d, const unsigned* a, const unsigned* b){
    asm volatile(
        "mma.sync.aligned.m16n8k16.row.col.f32.f16.f16.f32 "
        "{%0,%1,%2,%3}, {%4,%5,%6,%7}, {%8,%9}, {%0,%1,%2,%3};"
        : "+f"(d[0]), "+f"(d[1]), "+f"(d[2]), "+f"(d[3])
        : "r"(a[0]), "r"(a[1]), "r"(a[2]), "r"(a[3]), "r"(b[0]), "r"(b[1]));
}
// 64-byte rows, 16B-granule XOR swizzle: conflict-free ldmatrix
__device__ __forceinline__ unsigned swz(unsigned row, unsigned kb){
    return row * 64u + ((((kb >> 4) ^ ((row >> 1) & 3u)) << 4) | (kb & 15u));
}

// ---------------- conversion pre-passes --------------------------------------
__global__ __launch_bounds__(256) void conv_w(
    const float* __restrict__ Wq, const float* __restrict__ Wk,
    const float* __restrict__ Wv, const float* __restrict__ Wo)
{
    const int z = blockIdx.y;
    const float* W = (z == 0) ? Wq : (z == 1) ? Wk : (z == 2) ? Wv : Wo;
    const int i = blockIdx.x * 256 + threadIdx.x;
    float4 v = ((const float4*)W)[i];
    __half hx = __float2half(v.x), hy = __float2half(v.y);
    __half hz = __float2half(v.z), hw = __float2half(v.w);
    const size_t o = (size_t)z * (Dd*Dd) + (size_t)i * 4;
    *(__half2*)&g_wh[o]     = __halves2half2(hx, hy);
    *(__half2*)&g_wh[o + 2] = __halves2half2(hz, hw);
    *(__half2*)&g_wl[o]     = __halves2half2(__float2half(v.x - __half2float(hx)),
                                             __float2half(v.y - __half2float(hy)));
    *(__half2*)&g_wl[o + 2] = __halves2half2(__float2half(v.z - __half2float(hz)),
                                             __float2half(v.w - __half2float(hw)));
}

__global__ __launch_bounds__(256) void conv_in(
    const float* __restrict__ q, const float* __restrict__ k,
    const float* __restrict__ v)
{
    const int z = blockIdx.y;
    const float* X = (z == 0) ? q : (z == 1) ? k : v;
    const int i = blockIdx.x * 256 + threadIdx.x;
    if (z == 0 && i < NNODES) g_cnt[i] = 0;
    float4 val = ((const float4*)X)[i];
    const size_t o = (size_t)z * (MROWS*Dd) + (size_t)i * 4;
    *(__half2*)&g_ah[o]     = __floats2half2_rn(val.x, val.y);
    *(__half2*)&g_ah[o + 2] = __floats2half2_rn(val.z, val.w);
}

// ======== fp16 tensor-core GEMM (R14 config: BM=128, BN=64, BK=32) ===========
#define STG_BH 8192
#define STG_BL 12288
#define STAGE  16384

__global__ __launch_bounds__(256, 2) void gemm_tc(
    const float* __restrict__ B0, const float* __restrict__ B1,
    const float* __restrict__ B2, float* __restrict__ C_ext, int mode)
{
    extern __shared__ char dsm[];
    const unsigned sb = su32(dsm);

    const int z = blockIdx.z;
    const __half* A;
    const __half* Wh;
    const __half* Wl;
    const float* bias;
    float* dst;
    if (mode == 0) {
        A = g_ah + (size_t)z * (MROWS*Dd);
        Wh = g_wh + (size_t)z * (Dd*Dd);
        Wl = g_wl + (size_t)z * (Dd*Dd);
        bias = (z == 0) ? B0 : (z == 1) ? B1 : B2;
        dst = (z == 0) ? g_q : (z == 1) ? g_k : g_v;
    } else {
        A = g_atth;
        Wh = g_wh + (size_t)3 * (Dd*Dd);
        Wl = g_wl + (size_t)3 * (Dd*Dd);
        bias = B0;
        dst = C_ext;
    }

    const int tid = threadIdx.x;
    const int wid = tid >> 5, lane = tid & 31;
    const int wm = wid & 3, wn = wid >> 2;
    const int m0 = blockIdx.y * 128, n0 = blockIdx.x * 64;

    const int arow = tid >> 1;
    const int ap0 = (2 * tid) & 3;
    const int brow = tid >> 2, bp = tid & 3;
    const __half* Asrc = A + (size_t)(m0 + arow) * Dd + ap0 * 8;
    const __half* Whsrc = Wh + (size_t)(n0 + brow) * Dd + bp * 8;
    const __half* Wlsrc = Wl + (size_t)(n0 + brow) * Dd + bp * 8;
    const unsigned dA0 = swz(arow, ap0 * 16);
    const unsigned dA1 = swz(arow, ap0 * 16 + 16);
    const unsigned dB  = swz(brow, bp * 16);

    float acc[2][4][4];
#pragma unroll
    for (int mt = 0; mt < 2; mt++)
#pragma unroll
        for (int nt = 0; nt < 4; nt++)
#pragma unroll
            for (int i = 0; i < 4; i++) acc[mt][nt][i] = 0.f;

#pragma unroll
    for (int c = 0; c < 3; c++) {
        const unsigned st = sb + c * STAGE;
        cpa16(st + dA0, Asrc + c * 32);
        cpa16(st + dA1, Asrc + c * 32 + 8);
        cpa16(st + STG_BH + dB, Whsrc + c * 32);
        cpa16(st + STG_BL + dB, Wlsrc + c * 32);
        cpa_commit();
    }

    for (int c = 0; c < 16; c++) {
        cpa_wait2();
        __syncthreads();
        if (c + 3 < 16) {
            const unsigned st = sb + ((c + 3) & 3) * STAGE;
            cpa16(st + dA0, Asrc + (c + 3) * 32);
            cpa16(st + dA1, Asrc + (c + 3) * 32 + 8);
            cpa16(st + STG_BH + dB, Whsrc + (c + 3) * 32);
            cpa16(st + STG_BL + dB, Wlsrc + (c + 3) * 32);
        }
        cpa_commit();

        const unsigned st = sb + (c & 3) * STAGE;
#pragma unroll
        for (int ks = 0; ks < 2; ks++) {
            const unsigned kb = ks * 32;
            unsigned ah[2][4], bh[4][2], bl[4][2];
#pragma unroll
            for (int mt = 0; mt < 2; mt++) {
                unsigned r = wm * 32 + mt * 16 + (lane & 15);
                unsigned kbyte = kb + (lane >> 4) * 16;
                ldmx4(ah[mt], st + swz(r, kbyte));
            }
#pragma unroll
            for (int p = 0; p < 2; p++) {
                unsigned r = wn * 32 + p * 16 + (lane & 7) + ((lane >> 4) << 3);
                unsigned kbyte = kb + ((lane >> 3) & 1) * 16;
                unsigned t[4];
                ldmx4(t, st + STG_BH + swz(r, kbyte));
                bh[2*p][0] = t[0]; bh[2*p][1] = t[1];
                bh[2*p+1][0] = t[2]; bh[2*p+1][1] = t[3];
                ldmx4(t, st + STG_BL + swz(r, kbyte));
                bl[2*p][0] = t[0]; bl[2*p][1] = t[1];
                bl[2*p+1][0] = t[2]; bl[2*p+1][1] = t[3];
            }
#pragma unroll
            for (int mt = 0; mt < 2; mt++)
#pragma unroll
                for (int nt = 0; nt < 4; nt++) {
                    mma_f16(acc[mt][nt], ah[mt], bh[nt]);
                    mma_f16(acc[mt][nt], ah[mt], bl[nt]);
                }
        }
        __syncthreads();
    }

#pragma unroll
    for (int nt = 0; nt < 4; nt++) {
        const int ncol = n0 + wn * 32 + nt * 8 + 2 * (lane & 3);
        const float b0 = bias[ncol], b1 = bias[ncol + 1];
#pragma unroll
        for (int mt = 0; mt < 2; mt++) {
            const int r0 = m0 + wm * 32 + mt * 16 + (lane >> 2);
            float2 v0 = make_float2(acc[mt][nt][0] + b0, acc[mt][nt][1] + b1);
            float2 v1 = make_float2(acc[mt][nt][2] + b0, acc[mt][nt][3] + b1);
            if (mode == 1) {
                *(float2*)(dst + (size_t)r0 * Dd + ncol) = v0;
                *(float2*)(dst + (size_t)(r0 + 8) * Dd + ncol) = v1;
            } else {
                const int h = ncol >> 6, d = ncol & 63;
                int b = r0 >> 11, s = r0 & (Ss - 1);
                *(float2*)(dst + (size_t)(((b * Hh + h) * Ss + s)) * DK + d) = v0;
                b = (r0 + 8) >> 11; s = (r0 + 8) & (Ss - 1);
                *(float2*)(dst + (size_t)(((b * Hh + h) * Ss + s)) * DK + d) = v1;
            }
        }
    }
}

// ---------------- per-edge counting (index-only) -----------------------------
__global__ __launch_bounds__(256) void k_count(
    const int* __restrict__ snod, const int* __restrict__ enod)
{
    int t = blockIdx.x * 256 + threadIdx.x;       // 524288
    int jm = (t >> 11) & 7;
    int bh = t >> 14;
    int sv = snod[t];
    if (sv < 0) return;
    int ev = enod[t] & (Ss - 1);
    int sv2 = sv & (Ss - 1);
    int base = bh * Ss;
    if (jm != 0) atomicAdd(&g_cnt[base + ev], 1);
    atomicAdd(&g_cnt[base + sv2], 1);
}

// ---------------- exclusive scan of per-node counts per (b,h) --------------
__global__ __launch_bounds__(256) void k_scan()
{
    __shared__ int partial[256];
    int bh = blockIdx.x;
    int t = threadIdx.x;
    int base = bh * Ss + t * 8;
    int c[8]; int sum = 0;
#pragma unroll
    for (int i = 0; i < 8; i++) { c[i] = g_cnt[base + i]; sum += c[i]; }
    partial[t] = sum;
    __syncthreads();
    for (int off = 1; off < 256; off <<= 1) {
        int v = (t >= off) ? partial[t - off] : 0;
        __syncthreads();
        partial[t] += v;
        __syncthreads();
    }
    int run = partial[t] - sum;
    int obase = bh * (Ss + 1) + t * 8;
#pragma unroll
    for (int i = 0; i < 8; i++) { g_off[obase + i] = run; run += c[i]; }
    if (t == 255) g_off[bh * (Ss + 1) + Ss] = run;
#pragma unroll
    for (int i = 0; i < 8; i++) g_cnt[base + i] = 0;
}

// ---------------- CSR fill (info only) ---------------------------------------
__global__ __launch_bounds__(256) void k_fill(
    const int* __restrict__ snod, const int* __restrict__ enod)
{
    int t = blockIdx.x * 256 + threadIdx.x;       // 524288
    int jm = (t >> 11) & 7;
    int bh = t >> 14;
    int sv = snod[t];
    if (sv < 0) return;
    int ev = enod[t] & (Ss - 1);
    int sv2 = sv & (Ss - 1);
    int base = bh * Ss;
    int cbase = bh * (TR * Ss);
    if (jm != 0) {
        int pos = g_off[bh * (Ss + 1) + ev] + atomicAdd(&g_cnt[base + ev], 1);
        g_info[cbase + pos] = sv2 | (jm << 12);            // q=ev, k=sv, j=jm
    }
    {
        int pos = g_off[bh * (Ss + 1) + sv2] + atomicAdd(&g_cnt[base + sv2], 1);
        g_info[cbase + pos] = ev | ((jm + 8) << 12);       // q=sv, k=ev, j=jm+8
    }
}

// --------- per-node: score + softmax + weighted sum in ONE pass --------------
// warp per node, FOUR independent 8-lane groups over every 4th CSR entry.
// In-loop shuffles use GROUP-LOCAL masks (groups have different trip counts —
// full-warp masks would deadlock). Cross-group merge after loop reconvergence.
__global__ __launch_bounds__(256) void k_aggr(
    const float* __restrict__ rq, const float* __restrict__ rk,
    const float* __restrict__ rv)
{
    int w = (blockIdx.x * 256 + threadIdx.x) >> 5;
    int lane = threadIdx.x & 31;
    const int grp = lane >> 3;                    // 0..3
    const int gl = lane & 7;                      // lane within group
    const unsigned gmask = 0xFFu << (grp * 8);    // group-local mask
    int bh = w >> 11;
    int n = w & (Ss - 1);
    int h = bh & (Hh - 1), b = bh >> 3;
    int obase = bh * (Ss + 1) + n;
    int beg = g_off[obase], end = g_off[obase + 1];
    size_t qb = (size_t)(bh * Ss + n) * DK + 8 * gl;
    const float4 q0 = *(const float4*)&g_q[qb];
    const float4 q1 = *(const float4*)&g_q[qb + 4];
    float4 a0 = make_float4(0.f, 0.f, 0.f, 0.f);
    float4 a1 = make_float4(0.f, 0.f, 0.f, 0.f);
    float ds = 0.f;
    int cbase = bh * (TR * Ss);

    for (int i = beg + grp; i < end; i += 4) {
        int info = g_info[cbase + i];
        int kn = info & (Ss - 1);
        int j = info >> 12;
        size_t kb = (size_t)(bh * Ss + kn) * DK + 8 * gl;
        int rb = (h * TR + j) * DK + 8 * gl;
        float4 k0  = *(const float4*)&g_k[kb];
        float4 k1  = *(const float4*)&g_k[kb + 4];
        float4 rk0 = *(const float4*)&rk[rb];
        float4 rk1 = *(const float4*)&rk[rb + 4];
        float4 rq0 = *(const float4*)&rq[rb];
        float4 rq1 = *(const float4*)&rq[rb + 4];
        float p = q0.x * (k0.x + rk0.x) + rq0.x * k0.x
                + q0.y * (k0.y + rk0.y) + rq0.y * k0.y
                + q0.z * (k0.z + rk0.z) + rq0.z * k0.z
                + q0.w * (k0.w + rk0.w) + rq0.w * k0.w
                + q1.x * (k1.x + rk1.x) + rq1.x * k1.x
                + q1.y * (k1.y + rk1.y) + rq1.y * k1.y
                + q1.z * (k1.z + rk1.z) + rq1.z * k1.z
                + q1.w * (k1.w + rk1.w) + rq1.w * k1.w;
        p += __shfl_xor_sync(gmask, p, 4);
        p += __shfl_xor_sync(gmask, p, 2);
        p += __shfl_xor_sync(gmask, p, 1);
        float ev;
        if (gl == 0) ev = __expf(p * (1.0f / 24.0f));
        ev = __shfl_sync(gmask, ev, grp * 8);
        float4 v0  = *(const float4*)&g_v[kb];
        float4 v1  = *(const float4*)&g_v[kb + 4];
        float4 rv0 = *(const float4*)&rv[rb];
        float4 rv1 = *(const float4*)&rv[rb + 4];
        a0.x += ev * (v0.x + rv0.x);
        a0.y += ev * (v0.y + rv0.y);
        a0.z += ev * (v0.z + rv0.z);
        a0.w += ev * (v0.w + rv0.w);
        a1.x += ev * (v1.x + rv1.x);
        a1.y += ev * (v1.y + rv1.y);
        a1.z += ev * (v1.z + rv1.z);
        a1.w += ev * (v1.w + rv1.w);
        ds += ev;
    }
    // all lanes reconverged; merge the four groups (same dims in every group)
#pragma unroll
    for (int off = 8; off <= 16; off <<= 1) {
        a0.x += __shfl_xor_sync(0xffffffffu, a0.x, off);
        a0.y += __shfl_xor_sync(0xffffffffu, a0.y, off);
        a0.z += __shfl_xor_sync(0xffffffffu, a0.z, off);
        a0.w += __shfl_xor_sync(0xffffffffu, a0.w, off);
        a1.x += __shfl_xor_sync(0xffffffffu, a1.x, off);
        a1.y += __shfl_xor_sync(0xffffffffu, a1.y, off);
        a1.z += __shfl_xor_sync(0xffffffffu, a1.z, off);
        a1.w += __shfl_xor_sync(0xffffffffu, a1.w, off);
        ds   += __shfl_xor_sync(0xffffffffu, ds, off);
    }

    if (grp == 0) {
        float inv = ds > 0.f ? 1.f / ds : 0.f;
        size_t ob = (size_t)((b * Ss + n) * Hh + h) * DK + 8 * gl;
        __half2 o0 = __floats2half2_rn(a0.x * inv, a0.y * inv);
        __half2 o1 = __floats2half2_rn(a0.z * inv, a0.w * inv);
        __half2 o2 = __floats2half2_rn(a1.x * inv, a1.y * inv);
        __half2 o3 = __floats2half2_rn(a1.z * inv, a1.w * inv);
        uint4 ov;
        ov.x = *(unsigned*)&o0; ov.y = *(unsigned*)&o1;
        ov.z = *(unsigned*)&o2; ov.w = *(unsigned*)&o3;
        *(uint4*)&g_atth[ob] = ov;
    }
}

// ---------------- launch --------------------------------------------------
#define GEMM_SMEM (4 * STAGE)

extern "C" void kernel_launch(void* const* d_in, const int* in_sizes, int n_in,
                              void* d_out, int out_size)
{
    const float* query = (const float*)d_in[0];
    const float* key   = (const float*)d_in[1];
    const float* value = (const float*)d_in[2];
    const int*   snod  = (const int*)d_in[3];
    const int*   enod  = (const int*)d_in[4];
    const float* rel_q = (const float*)d_in[5];
    const float* rel_k = (const float*)d_in[6];
    const float* rel_v = (const float*)d_in[7];
    const float* Wq = (const float*)d_in[8];
    const float* bq = (const float*)d_in[9];
    const float* Wk = (const float*)d_in[10];
    const float* bk = (const float*)d_in[11];
    const float* Wv = (const float*)d_in[12];
    const float* bv = (const float*)d_in[13];
    const float* Wo = (const float*)d_in[14];
    const float* bo = (const float*)d_in[15];
    float* out = (float*)d_out;

    cudaFuncSetAttribute(gemm_tc, cudaFuncAttributeMaxDynamicSharedMemorySize, GEMM_SMEM);

    dim3 gcw(Dd * Dd / 4 / 256, 4);
    dim3 gci(MROWS * Dd / 4 / 256, 3);
    dim3 gq(Dd / 64, MROWS / 128, 3);
    dim3 go(Dd / 64, MROWS / 128, 1);

    conv_w<<<gcw, 256>>>(Wq, Wk, Wv, Wo);
    conv_in<<<gci, 256>>>(query, key, value);
    gemm_tc<<<gq, 256, GEMM_SMEM>>>(bq, bk, bv, nullptr, 0);
    k_count<<<(NBH * Rr * Ss) / 256, 256>>>(snod, enod);
    k_scan<<<NBH, 256>>>();
    k_fill<<<(NBH * Rr * Ss) / 256, 256>>>(snod, enod);
    k_aggr<<<NNODES * 32 / 256, 256>>>(rel_q, rel_k, rel_v);
    gemm_tc<<<go, 256, GEMM_SMEM>>>(bo, nullptr, nullptr, out, 1);
}